// round 1
// baseline (speedup 1.0000x reference)
#include <cuda_runtime.h>
#include <math.h>

#define N 4096
#define D 512
#define BM 128
#define BN 64
#define BK 16
#define TM 8
#define TN 4

// Scratch: row squared-norms (allocation-free per harness rules)
__device__ float g_norms[N];

// -------------------------------------------------------------------------
// Kernel 1: squared row norms. One warp per row, float4 loads.
// -------------------------------------------------------------------------
__global__ void norms_kernel(const float* __restrict__ x) {
    int row  = blockIdx.x * 8 + (threadIdx.x >> 5);   // 8 warps / block
    int lane = threadIdx.x & 31;
    const float4* xr = reinterpret_cast<const float4*>(x + row * D);
    float s = 0.f;
#pragma unroll
    for (int k = 0; k < (D / 4) / 32; k++) {          // 4 float4 per lane
        float4 v = xr[lane + k * 32];
        s += v.x * v.x + v.y * v.y + v.z * v.z + v.w * v.w;
    }
#pragma unroll
    for (int o = 16; o; o >>= 1) s += __shfl_xor_sync(0xffffffffu, s, o);
    if (lane == 0) g_norms[row] = s;
}

// -------------------------------------------------------------------------
// Kernel 2: lower-triangle Gram tiles -> distances.
// Tile (bi, bj): i in [128*bi, 128*bi+128), j in [64*bj, 64*bj+64).
// Tile needed iff bj <= 2*bi + 1. Row bi has (2*bi + 2) tiles,
// cumulative offset = bi*(bi+1). Total tiles = 32*33 = 1056.
// -------------------------------------------------------------------------
__global__ __launch_bounds__(256) void dist_kernel(const float* __restrict__ x,
                                                   float* __restrict__ out) {
    __shared__ float As[BK][BM];   // transposed: As[k][m]
    __shared__ float Bs[BK][BN];   // transposed: Bs[k][n]

    // linear block id -> (bi, bj) in the tile triangle
    int t  = blockIdx.x;
    int bi = (int)((sqrtf(4.0f * (float)t + 1.0f) - 1.0f) * 0.5f);
    while (bi * (bi + 1) > t)        bi--;
    while ((bi + 1) * (bi + 2) <= t) bi++;
    int bj = t - bi * (bi + 1);

    int i0 = bi * BM;
    int j0 = bj * BN;

    int tid = threadIdx.x;        // 256 threads = 16x16
    int tx  = tid & 15;
    int ty  = tid >> 4;

    float acc[TM][TN];
#pragma unroll
    for (int m = 0; m < TM; m++)
#pragma unroll
        for (int n = 0; n < TN; n++) acc[m][n] = 0.f;

    for (int kb = 0; kb < D; kb += BK) {
        __syncthreads();
        // Load A tile: 128 rows x 16 cols = 512 float4, 2 per thread
#pragma unroll
        for (int it = 0; it < 2; it++) {
            int f = tid + it * 256;
            int r = f >> 2;           // 0..127
            int q = f & 3;            // float4 index within the 16-col chunk
            float4 v = *reinterpret_cast<const float4*>(
                x + (size_t)(i0 + r) * D + kb + q * 4);
            As[q * 4 + 0][r] = v.x;
            As[q * 4 + 1][r] = v.y;
            As[q * 4 + 2][r] = v.z;
            As[q * 4 + 3][r] = v.w;
        }
        // Load B tile: 64 rows x 16 cols = 256 float4, 1 per thread
        {
            int r = tid >> 2;         // 0..63
            int q = tid & 3;
            float4 v = *reinterpret_cast<const float4*>(
                x + (size_t)(j0 + r) * D + kb + q * 4);
            Bs[q * 4 + 0][r] = v.x;
            Bs[q * 4 + 1][r] = v.y;
            Bs[q * 4 + 2][r] = v.z;
            Bs[q * 4 + 3][r] = v.w;
        }
        __syncthreads();

#pragma unroll
        for (int k = 0; k < BK; k++) {
            float4 a0 = *reinterpret_cast<const float4*>(&As[k][ty * TM]);
            float4 a1 = *reinterpret_cast<const float4*>(&As[k][ty * TM + 4]);
            float4 b0 = *reinterpret_cast<const float4*>(&Bs[k][tx * TN]);
            float a[TM] = {a0.x, a0.y, a0.z, a0.w, a1.x, a1.y, a1.z, a1.w};
            float b[TN] = {b0.x, b0.y, b0.z, b0.w};
#pragma unroll
            for (int m = 0; m < TM; m++)
#pragma unroll
                for (int n = 0; n < TN; n++)
                    acc[m][n] = fmaf(a[m], b[n], acc[m][n]);
        }
    }

    // Epilogue: d(i,j) = sqrt(max(ni + nj - 2*dot, 0)), out[i*(i-1)/2 + j], i>j
#pragma unroll
    for (int m = 0; m < TM; m++) {
        int i = i0 + ty * TM + m;
        float ni = g_norms[i];
        int ibase = (i * (i - 1)) >> 1;   // fits int32 for N=4096
#pragma unroll
        for (int n = 0; n < TN; n++) {
            int j = j0 + tx * TN + n;
            if (j < i) {
                float d2 = ni + g_norms[j] - 2.0f * acc[m][n];
                out[ibase + j] = sqrtf(fmaxf(d2, 0.0f));
            }
        }
    }
}

extern "C" void kernel_launch(void* const* d_in, const int* in_sizes, int n_in,
                              void* d_out, int out_size) {
    const float* x = (const float*)d_in[0];
    float* out = (float*)d_out;
    (void)in_sizes; (void)n_in; (void)out_size;

    norms_kernel<<<N / 8, 256>>>(x);

    int ntiles_i = N / BM;                       // 32
    int nblocks  = ntiles_i * (ntiles_i + 1);    // 1056
    dist_kernel<<<nblocks, 256>>>(x, out);
}

// round 4
// speedup vs baseline: 3.9353x; 3.9353x over previous
#include <cuda_runtime.h>
#include <cuda_bf16.h>
#include <cstdint>
#include <math.h>

#define NROWS 4096
#define DDIM  512
#define BM 128
#define BN 128
#define BK 32
#define NT   (NROWS / BM)            // 32
#define NBLK (NT * (NT + 1) / 2)     // 528
#define NCH  (DDIM / BK)             // 16
#define LDS  40                      // smem row stride in bf16 (80 B) -> conflict-free ldmatrix
#define TILE_ELEMS (BM * LDS)

__device__ __nv_bfloat16 g_xb[NROWS * DDIM];   // 4 MB bf16 copy of x
__device__ float g_norms[NROWS];

#define LDSM_X4(r, addr)                                                        \
    asm volatile("ldmatrix.sync.aligned.m8n8.x4.shared.b16 {%0,%1,%2,%3}, [%4];"\
        : "=r"((r)[0]), "=r"((r)[1]), "=r"((r)[2]), "=r"((r)[3]) : "r"(addr))
#define LDSM_X2(r, addr)                                                        \
    asm volatile("ldmatrix.sync.aligned.m8n8.x2.shared.b16 {%0,%1}, [%2];"      \
        : "=r"((r)[0]), "=r"((r)[1]) : "r"(addr))
#define MMA16816(c, a, b)                                                       \
    asm volatile("mma.sync.aligned.m16n8k16.row.col.f32.bf16.bf16.f32 "         \
        "{%0,%1,%2,%3}, {%4,%5,%6,%7}, {%8,%9}, {%0,%1,%2,%3};"                 \
        : "+f"((c)[0]), "+f"((c)[1]), "+f"((c)[2]), "+f"((c)[3])                \
        : "r"((a)[0]), "r"((a)[1]), "r"((a)[2]), "r"((a)[3]),                   \
          "r"((b)[0]), "r"((b)[1]))
#define CP_ASYNC16(dst, src)                                                    \
    asm volatile("cp.async.cg.shared.global [%0], [%1], 16;"                    \
        :: "r"(dst), "l"(src))

// ---------------------------------------------------------------------------
// Prep: fp32 norms + bf16 conversion. One warp per row.
// ---------------------------------------------------------------------------
__global__ __launch_bounds__(256) void prep_kernel(const float* __restrict__ x) {
    int row  = blockIdx.x * 8 + (threadIdx.x >> 5);
    int lane = threadIdx.x & 31;
    const float4* xr = reinterpret_cast<const float4*>(x + (size_t)row * DDIM);
    uint2* xo = reinterpret_cast<uint2*>(g_xb + (size_t)row * DDIM);
    float s = 0.f;
#pragma unroll
    for (int k = 0; k < 4; k++) {
        int idx = lane + k * 32;
        float4 v = xr[idx];
        s += v.x * v.x + v.y * v.y + v.z * v.z + v.w * v.w;
        __nv_bfloat162 p0 = __float22bfloat162_rn(make_float2(v.x, v.y));
        __nv_bfloat162 p1 = __float22bfloat162_rn(make_float2(v.z, v.w));
        uint2 o;
        o.x = *reinterpret_cast<uint32_t*>(&p0);
        o.y = *reinterpret_cast<uint32_t*>(&p1);
        xo[idx] = o;
    }
#pragma unroll
    for (int o = 16; o; o >>= 1) s += __shfl_xor_sync(0xffffffffu, s, o);
    if (lane == 0) g_norms[row] = s;
}

// ---------------------------------------------------------------------------
// Dist: 128x128 tiles over lower tile-triangle, bf16 mma.sync (HMMA.16816)
// ---------------------------------------------------------------------------
__global__ __launch_bounds__(256, 2) void dist_kernel(float* __restrict__ out) {
    __shared__ __align__(16) __nv_bfloat16 As[2][TILE_ELEMS];
    __shared__ __align__(16) __nv_bfloat16 Bs[2][TILE_ELEMS];

    int tid  = threadIdx.x;
    int lane = tid & 31;
    int wid  = tid >> 5;
    int wr   = wid >> 2;     // warp row 0..1 (64 rows each)
    int wc   = wid & 3;      // warp col 0..3 (32 cols each)

    // linear block id -> (bi, bj), bj <= bi
    int t  = blockIdx.x;
    int bi = (int)((sqrtf(8.0f * (float)t + 1.0f) - 1.0f) * 0.5f);
    while ((bi * (bi + 1)) / 2 > t)        bi--;
    while (((bi + 1) * (bi + 2)) / 2 <= t) bi++;
    int bj = t - (bi * (bi + 1)) / 2;
    int i0 = bi * BM;
    int j0 = bj * BN;

    const __nv_bfloat16* gA = g_xb + (size_t)i0 * DDIM;
    const __nv_bfloat16* gB = g_xb + (size_t)j0 * DDIM;

    float acc[4][4][4];
#pragma unroll
    for (int m = 0; m < 4; m++)
#pragma unroll
        for (int n = 0; n < 4; n++)
#pragma unroll
            for (int e = 0; e < 4; e++) acc[m][n][e] = 0.f;

    // per-thread load coords: 2 iters x (A,B); 16B each
    int r_ld = tid >> 2;         // 0..63  (rows r_ld and r_ld+64)
    int q_ld = tid & 3;          // 16B segment within 64B row chunk

    // issue chunk c into buffer b
    auto issue = [&](int c, int b) {
        int kb = c * BK;
#pragma unroll
        for (int it = 0; it < 2; it++) {
            int r = r_ld + it * 64;
            uint32_t da = (uint32_t)__cvta_generic_to_shared(
                &As[b][r * LDS + q_ld * 8]);
            CP_ASYNC16(da, gA + (size_t)r * DDIM + kb + q_ld * 8);
            uint32_t db = (uint32_t)__cvta_generic_to_shared(
                &Bs[b][r * LDS + q_ld * 8]);
            CP_ASYNC16(db, gB + (size_t)r * DDIM + kb + q_ld * 8);
        }
        asm volatile("cp.async.commit_group;");
    };

    // ldmatrix per-thread row/col offsets
    int arow = wr * 64 + (lane & 15);
    int akof = (lane >> 4) * 8;
    int brow = wc * 32 + (lane & 7);
    int bkof = ((lane >> 3) & 1) * 8;

    issue(0, 0);
    for (int c = 0; c < NCH; c++) {
        if (c + 1 < NCH) {
            issue(c + 1, (c + 1) & 1);
            asm volatile("cp.async.wait_group 1;");
        } else {
            asm volatile("cp.async.wait_group 0;");
        }
        __syncthreads();

        int b = c & 1;
        uint32_t aBase = (uint32_t)__cvta_generic_to_shared(&As[b][0]);
        uint32_t bBase = (uint32_t)__cvta_generic_to_shared(&Bs[b][0]);
#pragma unroll
        for (int ks = 0; ks < 2; ks++) {
            uint32_t afr[4][4], bfr[4][2];
#pragma unroll
            for (int mi = 0; mi < 4; mi++) {
                uint32_t ad = aBase +
                    (uint32_t)(((arow + mi * 16) * LDS + ks * 16 + akof) * 2);
                LDSM_X4(afr[mi], ad);
            }
#pragma unroll
            for (int ni = 0; ni < 4; ni++) {
                uint32_t bd = bBase +
                    (uint32_t)(((brow + ni * 8) * LDS + ks * 16 + bkof) * 2);
                LDSM_X2(bfr[ni], bd);
            }
#pragma unroll
            for (int mi = 0; mi < 4; mi++)
#pragma unroll
                for (int ni = 0; ni < 4; ni++)
                    MMA16816(acc[mi][ni], afr[mi], bfr[ni]);
        }
        __syncthreads();
    }

    // Epilogue: c-frag thread map: rows trow, trow+8; cols tcol, tcol+1
    int trow = lane >> 2;
    int tcol = (lane & 3) * 2;
#pragma unroll
    for (int mi = 0; mi < 4; mi++) {
#pragma unroll
        for (int half = 0; half < 2; half++) {
            int i = i0 + wr * 64 + mi * 16 + half * 8 + trow;
            float ni_ = g_norms[i];
            int ib = (i * (i - 1)) >> 1;
#pragma unroll
            for (int nj = 0; nj < 4; nj++) {
                int j = j0 + wc * 32 + nj * 8 + tcol;
                float c0 = acc[mi][nj][half * 2 + 0];
                float c1 = acc[mi][nj][half * 2 + 1];
                if (j < i)
                    out[ib + j] =
                        sqrtf(fmaxf(ni_ + g_norms[j] - 2.0f * c0, 0.0f));
                if (j + 1 < i)
                    out[ib + j + 1] =
                        sqrtf(fmaxf(ni_ + g_norms[j + 1] - 2.0f * c1, 0.0f));
            }
        }
    }
}

extern "C" void kernel_launch(void* const* d_in, const int* in_sizes, int n_in,
                              void* d_out, int out_size) {
    const float* x = (const float*)d_in[0];
    float* out = (float*)d_out;
    (void)in_sizes; (void)n_in; (void)out_size;

    prep_kernel<<<NROWS / 8, 256>>>(x);
    dist_kernel<<<NBLK, 256>>>(out);
}